// round 16
// baseline (speedup 1.0000x reference)
#include <cuda_runtime.h>
#include <cuda_fp16.h>
#include <math.h>
#include <stdint.h>

#define N_TOK   8192
#define D_MODEL 1024
#define H_DIM   512
#define N_EXP   8
#define TOPK    2
#define N_ASSIGN (N_TOK * TOPK)
#define TILE_M  128
#define MAX_TILES (N_ASSIGN / TILE_M + N_EXP)   // 136

// ------------------- device scratch -------------------
__device__ int   g_counts[N_EXP];
__device__ int   g_offsets[N_EXP + 1];
__device__ int   g_cursors[N_EXP];
__device__ int   g_rowToken[N_ASSIGN];
__device__ float g_tokw[N_TOK];
__device__ int   g_tokExperts[N_TOK * TOPK];
__device__ int   g_tileExpert[MAX_TILES];
__device__ int   g_tileRowStart[MAX_TILES];
__device__ int   g_tileRows[MAX_TILES];
__device__ int   g_numTiles;

// ------------------- helpers -------------------
__device__ __forceinline__ uint32_t f2tf(float f) {
    uint32_t u;
    asm("cvt.rna.tf32.f32 %0, %1;" : "=r"(u) : "f"(f));
    return u;
}
__device__ __forceinline__ uint32_t pack2h(float lo, float hi) {
    __half2 h = __floats2half2_rn(lo, hi);
    return *(uint32_t*)&h;
}
__device__ __forceinline__ void mma_tf32(float& c0, float& c1, float& c2, float& c3,
                                         uint32_t a0, uint32_t a1, uint32_t a2, uint32_t a3,
                                         uint32_t b0, uint32_t b1) {
    asm volatile("mma.sync.aligned.m16n8k8.row.col.f32.tf32.tf32.f32 "
                 "{%0,%1,%2,%3}, {%4,%5,%6,%7}, {%8,%9}, {%0,%1,%2,%3};"
                 : "+f"(c0), "+f"(c1), "+f"(c2), "+f"(c3)
                 : "r"(a0), "r"(a1), "r"(a2), "r"(a3), "r"(b0), "r"(b1));
}
__device__ __forceinline__ void mma_f16(float& c0, float& c1, float& c2, float& c3,
                                        uint32_t a0, uint32_t a1, uint32_t a2, uint32_t a3,
                                        uint32_t b0, uint32_t b1) {
    asm volatile("mma.sync.aligned.m16n8k16.row.col.f32.f16.f16.f32 "
                 "{%0,%1,%2,%3}, {%4,%5,%6,%7}, {%8,%9}, {%0,%1,%2,%3};"
                 : "+f"(c0), "+f"(c1), "+f"(c2), "+f"(c3)
                 : "r"(a0), "r"(a1), "r"(a2), "r"(a3), "r"(b0), "r"(b1));
}
__device__ __forceinline__ float gelu_exact(float v) {
    return 0.5f * v * (1.0f + erff(v * 0.70710678118654752f));
}

// ------------------- init: zero output + counters -------------------
__global__ void init_kernel(float* __restrict__ out) {
    int idx = blockIdx.x * blockDim.x + threadIdx.x;
    if (idx < (N_TOK * D_MODEL) / 4)
        ((float4*)out)[idx] = make_float4(0.f, 0.f, 0.f, 0.f);
    if (idx < N_EXP) g_counts[idx] = 0;
}

// ------------------- gating -------------------
__global__ void gate_kernel(const float* __restrict__ x, const float* __restrict__ gw) {
    int n = blockIdx.x;
    int tid = threadIdx.x;
    const float* xr = x + (size_t)n * D_MODEL;
    float acc[N_EXP];
#pragma unroll
    for (int e = 0; e < N_EXP; e++) acc[e] = 0.f;
    for (int d = tid; d < D_MODEL; d += 256) {
        float xv = xr[d];
        const float* g = gw + d * N_EXP;
#pragma unroll
        for (int e = 0; e < N_EXP; e++) acc[e] += xv * g[e];
    }
#pragma unroll
    for (int off = 16; off > 0; off >>= 1)
#pragma unroll
        for (int e = 0; e < N_EXP; e++)
            acc[e] += __shfl_down_sync(0xffffffffu, acc[e], off);
    __shared__ float s[8][N_EXP];
    int w = tid >> 5, l = tid & 31;
    if (l == 0)
#pragma unroll
        for (int e = 0; e < N_EXP; e++) s[w][e] = acc[e];
    __syncthreads();
    if (tid == 0) {
        float p[N_EXP];
#pragma unroll
        for (int e = 0; e < N_EXP; e++) {
            float v = 0.f;
#pragma unroll
            for (int ww = 0; ww < 8; ww++) v += s[ww][e];
            p[e] = v;
        }
        float mx = p[0];
#pragma unroll
        for (int e = 1; e < N_EXP; e++) mx = fmaxf(mx, p[e]);
        float sum = 0.f;
#pragma unroll
        for (int e = 0; e < N_EXP; e++) { p[e] = expf(p[e] - mx); sum += p[e]; }
        float inv = 1.f / sum;
#pragma unroll
        for (int e = 0; e < N_EXP; e++) p[e] *= inv;
        int i1 = 0;
#pragma unroll
        for (int e = 1; e < N_EXP; e++) if (p[e] > p[i1]) i1 = e;
        int i2 = (i1 == 0) ? 1 : 0;
#pragma unroll
        for (int e = 0; e < N_EXP; e++) if (e != i1 && p[e] > p[i2]) i2 = e;
        g_tokw[n] = p[i1] + p[i2];
        g_tokExperts[2 * n + 0] = i1;
        g_tokExperts[2 * n + 1] = i2;
        atomicAdd(&g_counts[i1], 1);
        atomicAdd(&g_counts[i2], 1);
    }
}

// ------------------- setup + scatter -------------------
__global__ void setup_kernel() {
    int off = 0;
    for (int e = 0; e < N_EXP; e++) { g_offsets[e] = off; g_cursors[e] = off; off += g_counts[e]; }
    g_offsets[N_EXP] = off;
    int t = 0;
    for (int e = 0; e < N_EXP; e++) {
        int c = g_counts[e];
        for (int r = 0; r < c; r += TILE_M) {
            g_tileExpert[t] = e; g_tileRowStart[t] = g_offsets[e] + r;
            g_tileRows[t] = min(TILE_M, c - r); t++;
        }
    }
    g_numTiles = t;
}
__global__ void scatter_kernel() {
    int n = blockIdx.x * blockDim.x + threadIdx.x;
    if (n >= N_TOK) return;
#pragma unroll
    for (int k = 0; k < TOPK; k++) {
        int e = g_tokExperts[2 * n + k];
        int pos = atomicAdd(&g_cursors[e], 1);
        g_rowToken[pos] = n;
    }
}

// ------------------- fused FFN kernel -------------------
// One CTA (512 threads, 16 warps) per 128-row expert tile. Grid = MAX_TILES (~1 wave).
// fc1: tf32 k8 GEMM (proven R4 maps), CTA tile 128x256, 2 passes over H=512; epilogue
//      bias+GELU+fp16-pack into SMEM h2 (128 rows x 260 half2-words, K-pair packed).
// fc2: fp16 k16 GEMM (proven R15 maps), A-frags straight from h2, B staged fp32->fp16,
//      CTA tile 128x256, 4 passes over D=1024; weighted atomicAdd epilogue.
#define FTHREADS 512
#define H2W     260
#define H2_WORDS (128 * H2W)          // 33280
#define AS_OFF  H2_WORDS
#define AS_ST   (128 * 20)            // 2560
#define BS_OFF  (AS_OFF + 2 * AS_ST)  // 38400
#define BS_ST   (16 * 264)            // 4224
#define BSH_OFF AS_OFF
#define BSH_ST  (16 * 264)
#define FUSED_SMEM_BYTES ((BS_OFF + 2 * BS_ST) * 4)   // 187392

__global__ void __launch_bounds__(FTHREADS, 1)
ffn_fused(const float* __restrict__ x,
          const float* __restrict__ w1, const float* __restrict__ b1,
          const float* __restrict__ w2, const float* __restrict__ b2,
          float* __restrict__ out) {
    int tile = blockIdx.x;
    if (tile >= g_numTiles) return;
    int e = g_tileExpert[tile], rs = g_tileRowStart[tile], nr = g_tileRows[tile];

    extern __shared__ uint32_t smw[];
    uint32_t* h2 = smw;
    uint32_t* As = smw + AS_OFF;
    uint32_t* Bs = smw + BS_OFF;
    uint32_t* Bsh = smw + BSH_OFF;

    int tid = threadIdx.x;
    int lane = tid & 31, wid = tid >> 5;
    int quad = lane >> 2, t4 = lane & 3;
    int wm = (wid & 1) * 64;
    int wn = (wid >> 1) * 32;

    int arow = tid >> 2;
    int aw = (tid & 3) * 4;
    bool avalid = arow < nr;
    const float* aptr = (avalid ? (x + (size_t)g_rowToken[rs + arow] * D_MODEL) : x) + aw;

    const float* w1e = w1 + (size_t)e * D_MODEL * H_DIM;
    int bcol = lane * 8;

    float c[4][4][4];

    // ==================== fc1 ====================
#pragma unroll 1
    for (int nh = 0; nh < 2; nh++) {
        const float* bbase = w1e + nh * 256 + bcol;
#pragma unroll
        for (int mi = 0; mi < 4; mi++)
#pragma unroll
            for (int ni = 0; ni < 4; ni++)
#pragma unroll
                for (int rr = 0; rr < 4; rr++) c[mi][ni][rr] = 0.f;

        {
            float4 av = avalid ? *(const float4*)(aptr) : make_float4(0, 0, 0, 0);
            *(uint4*)&As[arow * 20 + aw] =
                make_uint4(f2tf(av.x), f2tf(av.y), f2tf(av.z), f2tf(av.w));
            float4 b0 = *(const float4*)(bbase + (size_t)wid * H_DIM);
            float4 b1v = *(const float4*)(bbase + (size_t)wid * H_DIM + 4);
            *(uint4*)&Bs[wid * 264 + bcol] =
                make_uint4(f2tf(b0.x), f2tf(b0.y), f2tf(b0.z), f2tf(b0.w));
            *(uint4*)&Bs[wid * 264 + bcol + 4] =
                make_uint4(f2tf(b1v.x), f2tf(b1v.y), f2tf(b1v.z), f2tf(b1v.w));
        }
        __syncthreads();

        const int NT = D_MODEL / 16;
#pragma unroll 1
        for (int t = 0; t < NT; t++) {
            int s = t & 1;
            float4 na, nb0, nb1;
            bool more = (t + 1) < NT;
            if (more) {
                int k0 = (t + 1) * 16;
                na = avalid ? *(const float4*)(aptr + k0) : make_float4(0, 0, 0, 0);
                nb0 = *(const float4*)(bbase + (size_t)(k0 + wid) * H_DIM);
                nb1 = *(const float4*)(bbase + (size_t)(k0 + wid) * H_DIM + 4);
            }
            const uint32_t* Ass = As + s * AS_ST;
            const uint32_t* Bss = Bs + s * BS_ST;
#pragma unroll
            for (int kk = 0; kk < 2; kk++) {
                int k8 = kk * 8;
                uint32_t a[4][4], b[4][2];
#pragma unroll
                for (int mi = 0; mi < 4; mi++) {
                    int r0 = wm + mi * 16 + quad;
                    a[mi][0] = Ass[r0 * 20 + k8 + t4];
                    a[mi][1] = Ass[(r0 + 8) * 20 + k8 + t4];
                    a[mi][2] = Ass[r0 * 20 + k8 + t4 + 4];
                    a[mi][3] = Ass[(r0 + 8) * 20 + k8 + t4 + 4];
                }
#pragma unroll
                for (int ni = 0; ni < 4; ni++) {
                    int cc = wn + ni * 8 + quad;
                    b[ni][0] = Bss[(k8 + t4) * 264 + cc];
                    b[ni][1] = Bss[(k8 + t4 + 4) * 264 + cc];
                }
#pragma unroll
                for (int mi = 0; mi < 4; mi++)
#pragma unroll
                    for (int ni = 0; ni < 4; ni++)
                        mma_tf32(c[mi][ni][0], c[mi][ni][1], c[mi][ni][2], c[mi][ni][3],
                                 a[mi][0], a[mi][1], a[mi][2], a[mi][3],
                                 b[ni][0], b[ni][1]);
            }
            if (more) {
                int s1 = s ^ 1;
                *(uint4*)&As[s1 * AS_ST + arow * 20 + aw] =
                    make_uint4(f2tf(na.x), f2tf(na.y), f2tf(na.z), f2tf(na.w));
                *(uint4*)&Bs[s1 * BS_ST + wid * 264 + bcol] =
                    make_uint4(f2tf(nb0.x), f2tf(nb0.y), f2tf(nb0.z), f2tf(nb0.w));
                *(uint4*)&Bs[s1 * BS_ST + wid * 264 + bcol + 4] =
                    make_uint4(f2tf(nb1.x), f2tf(nb1.y), f2tf(nb1.z), f2tf(nb1.w));
            }
            __syncthreads();
        }

        const float* b1e = b1 + e * H_DIM + nh * 256;
#pragma unroll
        for (int mi = 0; mi < 4; mi++) {
#pragma unroll
            for (int half = 0; half < 2; half++) {
                int m = wm + mi * 16 + quad + half * 8;
                uint32_t* hrow = h2 + m * H2W + nh * 128;
#pragma unroll
                for (int ni = 0; ni < 4; ni++) {
                    int cc = wn + ni * 8 + 2 * t4;
                    float v0 = gelu_exact(c[mi][ni][half * 2 + 0] + b1e[cc]);
                    float v1 = gelu_exact(c[mi][ni][half * 2 + 1] + b1e[cc + 1]);
                    hrow[cc >> 1] = pack2h(v0, v1);
                }
            }
        }
    }

    // ==================== fc2 ====================
    const float* w2e = w2 + (size_t)e * H_DIM * D_MODEL;
    int k2r = wid;
    int n0w = lane * 8;

#pragma unroll 1
    for (int nq = 0; nq < 4; nq++) {
        const float* b2base = w2e + nq * 256 + n0w;
#pragma unroll
        for (int mi = 0; mi < 4; mi++)
#pragma unroll
            for (int ni = 0; ni < 4; ni++)
#pragma unroll
                for (int rr = 0; rr < 4; rr++) c[mi][ni][rr] = 0.f;

        {
            const float* lo = b2base + (size_t)(2 * k2r) * D_MODEL;
            const float* hi = lo + D_MODEL;
            float4 l0 = *(const float4*)(lo), l1 = *(const float4*)(lo + 4);
            float4 h0 = *(const float4*)(hi), h1 = *(const float4*)(hi + 4);
            *(uint4*)&Bsh[k2r * 264 + n0w] =
                make_uint4(pack2h(l0.x, h0.x), pack2h(l0.y, h0.y),
                           pack2h(l0.z, h0.z), pack2h(l0.w, h0.w));
            *(uint4*)&Bsh[k2r * 264 + n0w + 4] =
                make_uint4(pack2h(l1.x, h1.x), pack2h(l1.y, h1.y),
                           pack2h(l1.z, h1.z), pack2h(l1.w, h1.w));
        }
        __syncthreads();

        const int NT2 = H_DIM / 32;
#pragma unroll 1
        for (int t = 0; t < NT2; t++) {
            int s = t & 1;
            float4 l0, l1, h0, h1;
            bool more = (t + 1) < NT2;
            if (more) {
                int kb = (t + 1) * 32;
                const float* lo = b2base + (size_t)(kb + 2 * k2r) * D_MODEL;
                const float* hi = lo + D_MODEL;
                l0 = *(const float4*)(lo); l1 = *(const float4*)(lo + 4);
                h0 = *(const float4*)(hi); h1 = *(const float4*)(hi + 4);
            }
            const uint32_t* Bss = Bsh + s * BSH_ST;
#pragma unroll
            for (int kk = 0; kk < 2; kk++) {
                int kw = t * 16 + kk * 8;
                uint32_t a[4][4], b[4][2];
#pragma unroll
                for (int mi = 0; mi < 4; mi++) {
                    int r0 = wm + mi * 16 + quad;
                    a[mi][0] = h2[r0 * H2W + kw + t4];
                    a[mi][1] = h2[(r0 + 8) * H2W + kw + t4];
                    a[mi][2] = h2[r0 * H2W + kw + t4 + 4];
                    a[mi][3] = h2[(r0 + 8) * H2W + kw + t4 + 4];
                }
#pragma unroll
                for (int ni = 0; ni < 4; ni++) {
                    int cc = wn + ni * 8 + quad;
                    b[ni][0] = Bss[(kk * 8 + t4) * 264 + cc];
                    b[ni][1] = Bss[(kk * 8 + t4 + 4) * 264 + cc];
                }
#pragma unroll
                for (int mi = 0; mi < 4; mi++)
#pragma unroll
                    for (int ni = 0; ni < 4; ni++)
                        mma_f16(c[mi][ni][0], c[mi][ni][1], c[mi][ni][2], c[mi][ni][3],
                                a[mi][0], a[mi][1], a[mi][2], a[mi][3],
                                b[ni][0], b[ni][1]);
            }
            if (more) {
                int s1 = s ^ 1;
                *(uint4*)&Bsh[s1 * BSH_ST + k2r * 264 + n0w] =
                    make_uint4(pack2h(l0.x, h0.x), pack2h(l0.y, h0.y),
                               pack2h(l0.z, h0.z), pack2h(l0.w, h0.w));
                *(uint4*)&Bsh[s1 * BSH_ST + k2r * 264 + n0w + 4] =
                    make_uint4(pack2h(l1.x, h1.x), pack2h(l1.y, h1.y),
                               pack2h(l1.z, h1.z), pack2h(l1.w, h1.w));
            }
            __syncthreads();
        }

        const float* b2e = b2 + e * D_MODEL + nq * 256;
#pragma unroll
        for (int mi = 0; mi < 4; mi++) {
#pragma unroll
            for (int half = 0; half < 2; half++) {
                int m = wm + mi * 16 + quad + half * 8;
                if (m < nr) {
                    int token = g_rowToken[rs + m];
                    float wgt = g_tokw[token];
                    float* orow = out + (size_t)token * D_MODEL + nq * 256;
#pragma unroll
                    for (int ni = 0; ni < 4; ni++) {
                        int cc = wn + ni * 8 + 2 * t4;
                        float v0 = c[mi][ni][half * 2 + 0] + b2e[cc];
                        float v1 = c[mi][ni][half * 2 + 1] + b2e[cc + 1];
                        atomicAdd(&orow[cc], wgt * v0);
                        atomicAdd(&orow[cc + 1], wgt * v1);
                    }
                }
            }
        }
    }
}

// ------------------- launch -------------------
extern "C" void kernel_launch(void* const* d_in, const int* in_sizes, int n_in,
                              void* d_out, int out_size) {
    const float* x      = (const float*)d_in[0];
    const float* gate_w = (const float*)d_in[1];
    const float* w1     = (const float*)d_in[2];
    const float* b1     = (const float*)d_in[3];
    const float* w2     = (const float*)d_in[4];
    const float* b2     = (const float*)d_in[5];
    float* out = (float*)d_out;

    static bool attr_done = false;
    if (!attr_done) {
        cudaFuncSetAttribute(ffn_fused, cudaFuncAttributeMaxDynamicSharedMemorySize,
                             FUSED_SMEM_BYTES);
        attr_done = true;
    }

    init_kernel<<<(N_TOK * D_MODEL / 4 + 255) / 256, 256>>>(out);
    gate_kernel<<<N_TOK, 256>>>(x, gate_w);
    setup_kernel<<<1, 1>>>();
    scatter_kernel<<<(N_TOK + 255) / 256, 256>>>();
    ffn_fused<<<MAX_TILES, FTHREADS, FUSED_SMEM_BYTES>>>(x, w1, b1, w2, b2, out);
}

// round 17
// speedup vs baseline: 1.2502x; 1.2502x over previous
#include <cuda_runtime.h>
#include <math.h>
#include <stdint.h>

#define N_TOK   8192
#define D_MODEL 1024
#define H_DIM   512
#define N_EXP   8
#define TOPK    2
#define N_ASSIGN (N_TOK * TOPK)
#define TILE_M  128
#define MAX_TILES (N_ASSIGN / TILE_M + N_EXP)   // 136

// ------------------- device scratch -------------------
__device__ float g_h[(size_t)N_ASSIGN * H_DIM];
__device__ int   g_counts[N_EXP];
__device__ int   g_offsets[N_EXP + 1];
__device__ int   g_cursors[N_EXP];
__device__ int   g_rowToken[N_ASSIGN];
__device__ float g_tokw[N_TOK];
__device__ int   g_tokExperts[N_TOK * TOPK];
__device__ int   g_tileExpert[MAX_TILES];
__device__ int   g_tileRowStart[MAX_TILES];
__device__ int   g_tileRows[MAX_TILES];
__device__ int   g_numTiles;

// ------------------- helpers -------------------
__device__ __forceinline__ uint32_t f2tf(float f) {
    uint32_t u;
    asm("cvt.rna.tf32.f32 %0, %1;" : "=r"(u) : "f"(f));
    return u;
}
__device__ __forceinline__ void mma_tf32(float& c0, float& c1, float& c2, float& c3,
                                         uint32_t a0, uint32_t a1, uint32_t a2, uint32_t a3,
                                         uint32_t b0, uint32_t b1) {
    asm volatile("mma.sync.aligned.m16n8k8.row.col.f32.tf32.tf32.f32 "
                 "{%0,%1,%2,%3}, {%4,%5,%6,%7}, {%8,%9}, {%0,%1,%2,%3};"
                 : "+f"(c0), "+f"(c1), "+f"(c2), "+f"(c3)
                 : "r"(a0), "r"(a1), "r"(a2), "r"(a3), "r"(b0), "r"(b1));
}
__device__ __forceinline__ float gelu_exact(float v) {
    return 0.5f * v * (1.0f + erff(v * 0.70710678118654752f));
}

// ------------------- tiny init: counters only -------------------
__global__ void init_counts_kernel() {
    if (threadIdx.x < N_EXP) g_counts[threadIdx.x] = 0;
}

// ------------------- gating + output zeroing (block n owns token n) -------------------
__global__ void gate_kernel(const float* __restrict__ x, const float* __restrict__ gw,
                            float* __restrict__ out) {
    int n = blockIdx.x;
    int tid = threadIdx.x;

    // zero this token's output row: 1024 floats = 256 threads x float4
    ((float4*)(out + (size_t)n * D_MODEL))[tid] = make_float4(0.f, 0.f, 0.f, 0.f);

    const float* xr = x + (size_t)n * D_MODEL;
    float acc[N_EXP];
#pragma unroll
    for (int e = 0; e < N_EXP; e++) acc[e] = 0.f;
    for (int d = tid; d < D_MODEL; d += 256) {
        float xv = xr[d];
        const float* g = gw + d * N_EXP;
#pragma unroll
        for (int e = 0; e < N_EXP; e++) acc[e] += xv * g[e];
    }
#pragma unroll
    for (int off = 16; off > 0; off >>= 1)
#pragma unroll
        for (int e = 0; e < N_EXP; e++)
            acc[e] += __shfl_down_sync(0xffffffffu, acc[e], off);
    __shared__ float s[8][N_EXP];
    int w = tid >> 5, l = tid & 31;
    if (l == 0)
#pragma unroll
        for (int e = 0; e < N_EXP; e++) s[w][e] = acc[e];
    __syncthreads();
    if (tid == 0) {
        float p[N_EXP];
#pragma unroll
        for (int e = 0; e < N_EXP; e++) {
            float v = 0.f;
#pragma unroll
            for (int ww = 0; ww < 8; ww++) v += s[ww][e];
            p[e] = v;
        }
        float mx = p[0];
#pragma unroll
        for (int e = 1; e < N_EXP; e++) mx = fmaxf(mx, p[e]);
        float sum = 0.f;
#pragma unroll
        for (int e = 0; e < N_EXP; e++) { p[e] = expf(p[e] - mx); sum += p[e]; }
        float inv = 1.f / sum;
#pragma unroll
        for (int e = 0; e < N_EXP; e++) p[e] *= inv;
        int i1 = 0;
#pragma unroll
        for (int e = 1; e < N_EXP; e++) if (p[e] > p[i1]) i1 = e;
        int i2 = (i1 == 0) ? 1 : 0;
#pragma unroll
        for (int e = 0; e < N_EXP; e++) if (e != i1 && p[e] > p[i2]) i2 = e;
        g_tokw[n] = p[i1] + p[i2];
        g_tokExperts[2 * n + 0] = i1;
        g_tokExperts[2 * n + 1] = i2;
        atomicAdd(&g_counts[i1], 1);
        atomicAdd(&g_counts[i2], 1);
    }
}

// ------------------- setup + scatter -------------------
__global__ void setup_kernel() {
    int off = 0;
    for (int e = 0; e < N_EXP; e++) { g_offsets[e] = off; g_cursors[e] = off; off += g_counts[e]; }
    g_offsets[N_EXP] = off;
    int t = 0;
    for (int e = 0; e < N_EXP; e++) {
        int c = g_counts[e];
        for (int r = 0; r < c; r += TILE_M) {
            g_tileExpert[t] = e; g_tileRowStart[t] = g_offsets[e] + r;
            g_tileRows[t] = min(TILE_M, c - r); t++;
        }
    }
    g_numTiles = t;
}
__global__ void scatter_kernel() {
    int n = blockIdx.x * blockDim.x + threadIdx.x;
    if (n >= N_TOK) return;
#pragma unroll
    for (int k = 0; k < TOPK; k++) {
        int e = g_tokExperts[2 * n + k];
        int pos = atomicAdd(&g_cursors[e], 1);
        g_rowToken[pos] = n;
    }
}

// ------------------- tf32 mma.sync grouped GEMM (R4-champion core, untouched) -------
// Tile 128(M) x 128(N), BK=16. 8 warps: warp_m = wid&1 (x64), warp_n = wid>>1 (x32).
// Warp tile 64x32 -> 4x4 grid of m16n8k8.
// SMEM: As[2][128][20] (bank=4m+k, conflict-free), Bs[2][16][136] (bank=8k+n, conflict-free).
#define BK 16
#define ASTR 20
#define BSTR 136

struct Frag { float c[4][4][4]; };  // [mi][ni][reg]

template <int KDIM, bool FC1>
__device__ __forceinline__ void gemm_core(
    const float* __restrict__ aBase,   // FC1: x (gathered); FC2: g_h
    const float* __restrict__ bBase,   // weight [KDIM][N_total] row-major for this expert
    int nTotal, int n0, int rs, int nr, Frag& F)
{
    __shared__ uint32_t As[2][128][ASTR];
    __shared__ uint32_t Bs[2][BK][BSTR];

    int tid = threadIdx.x;
    int lane = tid & 31, wid = tid >> 5;
    int quad = lane >> 2, t4 = lane & 3;
    int wm = (wid & 1) * 64, wn = (wid >> 1) * 32;

    // A gather setup: 2 threads per row, 8 floats (2 float4) each
    int arow = tid >> 1;
    int acol0 = (tid & 1) * 8;
    const float* aptr;
    bool avalid;
    if (FC1) {
        avalid = arow < nr;
        aptr = avalid ? (aBase + (size_t)g_rowToken[rs + arow] * KDIM) : aBase;
    } else {
        avalid = true;
        int ar = rs + arow; if (ar >= N_ASSIGN) ar = N_ASSIGN - 1;
        aptr = aBase + (size_t)ar * KDIM;
    }
    // B: 16 threads/row group: row = tid>>4 (0..15), 2 float4 at cols (tid&15)*8
    int brow = tid >> 4;
    int bcol0 = (tid & 15) * 8;
    const float* bptr = bBase + (size_t)brow * nTotal + n0 + bcol0;

#pragma unroll
    for (int mi = 0; mi < 4; mi++)
#pragma unroll
        for (int ni = 0; ni < 4; ni++)
#pragma unroll
            for (int rr = 0; rr < 4; rr++) F.c[mi][ni][rr] = 0.f;

    // ---- prologue: load tile 0 ----
    {
#pragma unroll
        for (int j = 0; j < 2; j++) {
            float4 v = avalid ? *(const float4*)(aptr + acol0 + j * 4)
                              : make_float4(0.f, 0.f, 0.f, 0.f);
            uint32_t* d = &As[0][arow][acol0 + j * 4];
            d[0] = f2tf(v.x); d[1] = f2tf(v.y); d[2] = f2tf(v.z); d[3] = f2tf(v.w);
        }
#pragma unroll
        for (int j = 0; j < 2; j++) {
            float4 v = *(const float4*)(bptr + j * 4);
            uint32_t* d = &Bs[0][brow][bcol0 + j * 4];
            d[0] = f2tf(v.x); d[1] = f2tf(v.y); d[2] = f2tf(v.z); d[3] = f2tf(v.w);
        }
    }
    __syncthreads();

    const int NT = KDIM / BK;
    for (int t = 0; t < NT; t++) {
        int s = t & 1;
        float4 na[2], nb[2];
        bool more = (t + 1) < NT;
        if (more) {
            int k0 = (t + 1) * BK;
#pragma unroll
            for (int j = 0; j < 2; j++)
                na[j] = avalid ? *(const float4*)(aptr + k0 + acol0 + j * 4)
                               : make_float4(0.f, 0.f, 0.f, 0.f);
#pragma unroll
            for (int j = 0; j < 2; j++)
                nb[j] = *(const float4*)(bptr + (size_t)k0 * nTotal + j * 4);
        }
        // ---- compute on stage s ----
#pragma unroll
        for (int kk = 0; kk < BK / 8; kk++) {
            uint32_t a[4][4], b[4][2];
#pragma unroll
            for (int mi = 0; mi < 4; mi++) {
                int r0 = wm + mi * 16 + quad;
                a[mi][0] = As[s][r0][kk * 8 + t4];
                a[mi][1] = As[s][r0 + 8][kk * 8 + t4];
                a[mi][2] = As[s][r0][kk * 8 + t4 + 4];
                a[mi][3] = As[s][r0 + 8][kk * 8 + t4 + 4];
            }
#pragma unroll
            for (int ni = 0; ni < 4; ni++) {
                int cc = wn + ni * 8 + quad;
                b[ni][0] = Bs[s][kk * 8 + t4][cc];
                b[ni][1] = Bs[s][kk * 8 + t4 + 4][cc];
            }
#pragma unroll
            for (int mi = 0; mi < 4; mi++)
#pragma unroll
                for (int ni = 0; ni < 4; ni++)
                    mma_tf32(F.c[mi][ni][0], F.c[mi][ni][1], F.c[mi][ni][2], F.c[mi][ni][3],
                             a[mi][0], a[mi][1], a[mi][2], a[mi][3],
                             b[ni][0], b[ni][1]);
        }
        // ---- store next stage ----
        if (more) {
            int s1 = s ^ 1;
#pragma unroll
            for (int j = 0; j < 2; j++) {
                uint32_t* d = &As[s1][arow][acol0 + j * 4];
                d[0] = f2tf(na[j].x); d[1] = f2tf(na[j].y); d[2] = f2tf(na[j].z); d[3] = f2tf(na[j].w);
            }
#pragma unroll
            for (int j = 0; j < 2; j++) {
                uint32_t* d = &Bs[s1][brow][bcol0 + j * 4];
                d[0] = f2tf(nb[j].x); d[1] = f2tf(nb[j].y); d[2] = f2tf(nb[j].z); d[3] = f2tf(nb[j].w);
            }
        }
        __syncthreads();
    }
}

// fc1: h = gelu(x_gathered @ w1[e] + b1[e]); grid (MAX_TILES, H_DIM/128)
__global__ void __launch_bounds__(256, 2)
fc1_mma(const float* __restrict__ x, const float* __restrict__ w1,
        const float* __restrict__ b1) {
    int tile = blockIdx.x;
    if (tile >= g_numTiles) return;
    int e = g_tileExpert[tile], rs = g_tileRowStart[tile], nr = g_tileRows[tile];
    int n0 = blockIdx.y * 128;

    Frag F;
    gemm_core<D_MODEL, true>(x, w1 + (size_t)e * D_MODEL * H_DIM, H_DIM, n0, rs, nr, F);

    int tid = threadIdx.x, lane = tid & 31, wid = tid >> 5;
    int quad = lane >> 2, t4 = lane & 3;
    int wm = (wid & 1) * 64, wn = (wid >> 1) * 32;
    const float* b1e = b1 + e * H_DIM + n0;
#pragma unroll
    for (int mi = 0; mi < 4; mi++) {
#pragma unroll
        for (int half = 0; half < 2; half++) {
            int m = wm + mi * 16 + quad + half * 8;
            if (m < nr) {
                float* hrow = g_h + (size_t)(rs + m) * H_DIM + n0;
#pragma unroll
                for (int ni = 0; ni < 4; ni++) {
                    int cc = wn + ni * 8 + 2 * t4;
                    float v0 = F.c[mi][ni][half * 2 + 0] + b1e[cc];
                    float v1 = F.c[mi][ni][half * 2 + 1] + b1e[cc + 1];
                    *(float2*)(hrow + cc) = make_float2(gelu_exact(v0), gelu_exact(v1));
                }
            }
        }
    }
}

// fc2: out[token] += tokw * (h @ w2[e] + b2[e]); grid (MAX_TILES, D_MODEL/128)
__global__ void __launch_bounds__(256, 2)
fc2_mma(const float* __restrict__ w2, const float* __restrict__ b2,
        float* __restrict__ out) {
    int tile = blockIdx.x;
    if (tile >= g_numTiles) return;
    int e = g_tileExpert[tile], rs = g_tileRowStart[tile], nr = g_tileRows[tile];
    int n0 = blockIdx.y * 128;

    Frag F;
    gemm_core<H_DIM, false>(g_h, w2 + (size_t)e * H_DIM * D_MODEL, D_MODEL, n0, rs, nr, F);

    int tid = threadIdx.x, lane = tid & 31, wid = tid >> 5;
    int quad = lane >> 2, t4 = lane & 3;
    int wm = (wid & 1) * 64, wn = (wid >> 1) * 32;
    const float* b2e = b2 + e * D_MODEL + n0;
#pragma unroll
    for (int mi = 0; mi < 4; mi++) {
#pragma unroll
        for (int half = 0; half < 2; half++) {
            int m = wm + mi * 16 + quad + half * 8;
            if (m < nr) {
                int token = g_rowToken[rs + m];
                float wgt = g_tokw[token];
                float* orow = out + (size_t)token * D_MODEL + n0;
#pragma unroll
                for (int ni = 0; ni < 4; ni++) {
                    int cc = wn + ni * 8 + 2 * t4;
                    float v0 = F.c[mi][ni][half * 2 + 0] + b2e[cc];
                    float v1 = F.c[mi][ni][half * 2 + 1] + b2e[cc + 1];
                    atomicAdd(&orow[cc], wgt * v0);
                    atomicAdd(&orow[cc + 1], wgt * v1);
                }
            }
        }
    }
}

// ------------------- launch -------------------
extern "C" void kernel_launch(void* const* d_in, const int* in_sizes, int n_in,
                              void* d_out, int out_size) {
    const float* x      = (const float*)d_in[0];
    const float* gate_w = (const float*)d_in[1];
    const float* w1     = (const float*)d_in[2];
    const float* b1     = (const float*)d_in[3];
    const float* w2     = (const float*)d_in[4];
    const float* b2     = (const float*)d_in[5];
    float* out = (float*)d_out;

    init_counts_kernel<<<1, 32>>>();
    gate_kernel<<<N_TOK, 256>>>(x, gate_w, out);   // also zeroes out rows
    setup_kernel<<<1, 1>>>();
    scatter_kernel<<<(N_TOK + 255) / 256, 256>>>();
    {
        dim3 g(MAX_TILES, H_DIM / 128);
        fc1_mma<<<g, 256>>>(x, w1, b1);
    }
    {
        dim3 g(MAX_TILES, D_MODEL / 128);
        fc2_mma<<<g, 256>>>(w2, b2, out);
    }
}